// round 15
// baseline (speedup 1.0000x reference)
#include <cuda_runtime.h>
#include <cuda_fp16.h>

#define BATCH 4
#define SEQ   2048
#define DM    1024
#define NH    16
#define DKH   64
#define MROWS (BATCH*SEQ)      // 8192
#define NELEM (MROWS*DM)       // 8388608
#define WELEM (DM*DM)          // 1048576

// ---------------------------------------------------------------------------
// Scratch planes (device globals: allocation-free per harness rules)
// ---------------------------------------------------------------------------
__device__ __half g_xq[NELEM], g_xk[NELEM], g_xv[NELEM];   // fp16 inputs
__device__ __half g_wq[WELEM], g_wk[WELEM];                // fp16 of w*1024
__device__ __half g_wv[WELEM], g_wo[WELEM];
__device__ __half g_Qf[NELEM], g_Kf[NELEM], g_Vf[NELEM];   // projected (Q pre-scaled)
__device__ __half g_Of[NELEM];                             // attention output

// ---------------------------------------------------------------------------
// helpers
// ---------------------------------------------------------------------------
__device__ __forceinline__ unsigned pack2h(float e0, float e1){
    unsigned r; asm("cvt.rn.f16x2.f32 %0, %1, %2;" : "=r"(r) : "f"(e1), "f"(e0));
    return r;   // lo half = f16(e0), hi half = f16(e1)
}
__device__ __forceinline__ void mma16h(float c[4], const unsigned a[4],
                                       unsigned b0, unsigned b1){
    asm volatile("mma.sync.aligned.m16n8k16.row.col.f32.f16.f16.f32 "
        "{%0,%1,%2,%3},{%4,%5,%6,%7},{%8,%9},{%0,%1,%2,%3};\n"
        : "+f"(c[0]),"+f"(c[1]),"+f"(c[2]),"+f"(c[3])
        : "r"(a[0]),"r"(a[1]),"r"(a[2]),"r"(a[3]),"r"(b0),"r"(b1));
}
__device__ __forceinline__ void ldsm4(unsigned r[4], const void* p){
    unsigned addr = (unsigned)__cvta_generic_to_shared(p);
    asm volatile("ldmatrix.sync.aligned.m8n8.x4.shared.b16 {%0,%1,%2,%3},[%4];"
        : "=r"(r[0]),"=r"(r[1]),"=r"(r[2]),"=r"(r[3]) : "r"(addr));
}
__device__ __forceinline__ void ldsm4t(unsigned r[4], const void* p){
    unsigned addr = (unsigned)__cvta_generic_to_shared(p);
    asm volatile("ldmatrix.sync.aligned.m8n8.x4.trans.shared.b16 {%0,%1,%2,%3},[%4];"
        : "=r"(r[0]),"=r"(r[1]),"=r"(r[2]),"=r"(r[3]) : "r"(addr));
}
__device__ __forceinline__ void cp16(const void* smem_dst, const void* gmem_src){
    unsigned d = (unsigned)__cvta_generic_to_shared(smem_dst);
    asm volatile("cp.async.cg.shared.global [%0],[%1],16;" :: "r"(d), "l"(gmem_src));
}
__device__ __forceinline__ void cpcommit(){ asm volatile("cp.async.commit_group;"); }
template<int N> __device__ __forceinline__ void cpwait(){
    asm volatile("cp.async.wait_group %0;" :: "n"(N));
}

// ---------------------------------------------------------------------------
// converts: fp32 -> fp16 (inputs, scale=1) and weights (scale=1024)
// grid.z picks the array.
// ---------------------------------------------------------------------------
__global__ __launch_bounds__(256) void conv_in(
    const float4* __restrict__ s0, const float4* __restrict__ s1,
    const float4* __restrict__ s2,
    uint2* __restrict__ d0, uint2* __restrict__ d1, uint2* __restrict__ d2,
    int n4)
{
    const float4* src = (blockIdx.z==0)?s0:(blockIdx.z==1)?s1:s2;
    uint2* dst = (blockIdx.z==0)?d0:(blockIdx.z==1)?d1:d2;
    const int base = blockIdx.x * (blockDim.x * 4) + threadIdx.x;
    #pragma unroll
    for (int j = 0; j < 4; j++){
        const int i = base + j * blockDim.x;
        if (i < n4){
            float4 v = src[i];
            dst[i] = make_uint2(pack2h(v.x, v.y), pack2h(v.z, v.w));
        }
    }
}

__global__ __launch_bounds__(256) void conv_w(
    const float4* __restrict__ s0, const float4* __restrict__ s1,
    const float4* __restrict__ s2, const float4* __restrict__ s3,
    uint2* __restrict__ d0, uint2* __restrict__ d1,
    uint2* __restrict__ d2, uint2* __restrict__ d3,
    int n4)
{
    const int z = blockIdx.z;
    const float4* src = (z==0)?s0:(z==1)?s1:(z==2)?s2:s3;
    uint2* dst = (z==0)?d0:(z==1)?d1:(z==2)?d2:d3;
    const int base = blockIdx.x * (blockDim.x * 4) + threadIdx.x;
    #pragma unroll
    for (int j = 0; j < 4; j++){
        const int i = base + j * blockDim.x;
        if (i < n4){
            float4 v = src[i];
            dst[i] = make_uint2(pack2h(v.x*1024.f, v.y*1024.f),
                                pack2h(v.z*1024.f, v.w*1024.f));
        }
    }
}

// ---------------------------------------------------------------------------
// FP16 GEMM: C[m,n] = (sum_k A[m,k]*Ws[n,k])/1024 + bias[n],  Ws = w*1024.
// 128x128x32 tiles, 256 thr, 8 warps (64x32), cp.async 2-stage.
// OMODE 0: fp32 C.  OMODE 1: fp16 Cf, result scaled by ga.scale.
// ---------------------------------------------------------------------------
#define GS2  40                 // fp16 elems per smem row (80B)
#define GPL  (128*GS2)          // elems per plane (5120)
#define GSTG (2*GPL)            // stage: Af|Bf (10240)

struct GemmArgs {
    const __half *Af, *Bf;
    const float* bias;
    float* C;
    __half* Cf;
    float scale;
};

template<int OMODE>
__device__ __forceinline__ void gemm1h_body(const GemmArgs& ga, int M, int N, int K)
{
    extern __shared__ __half smh[];
    const int tid  = threadIdx.x;
    const int warp = tid >> 5, lane = tid & 31;
    const int g = lane >> 2, t4 = lane & 3;
    const int lr = lane & 7, grp = lane >> 3;
    const int warpM = (warp >> 2) * 64;
    const int warpN = (warp & 3) * 32;
    const int m0 = blockIdx.y * 128, n0 = blockIdx.x * 128;

    float acc[4][4][4];
    #pragma unroll
    for (int i=0;i<4;i++)
        #pragma unroll
        for (int j=0;j<4;j++)
            #pragma unroll
            for (int c=0;c<4;c++) acc[i][j][c] = 0.f;

    auto issue = [&](int kt){
        const int st = (kt & 1) * GSTG;
        #pragma unroll
        for (int pl = 0; pl < 2; pl++){
            const __half* base = (pl==0)?ga.Af:ga.Bf;
            const int rb = (pl == 0) ? m0 : n0;
            #pragma unroll
            for (int j = 0; j < 2; j++){
                const int cc = j*256 + tid;
                const int r = cc >> 2, col = (cc & 3) * 8;
                cp16(smh + st + pl*GPL + r*GS2 + col,
                     base + (size_t)(rb + r)*K + kt*32 + col);
            }
        }
        cpcommit();
    };

    const int KT = K >> 5;
    issue(0);

    for (int kt = 0; kt < KT; kt++){
        if (kt + 1 < KT){ issue(kt+1); cpwait<1>(); } else cpwait<0>();
        __syncthreads();

        const __half* S   = smh + (kt & 1) * GSTG;
        const __half* SAf = S;
        const __half* SBf = S + GPL;

        #pragma unroll
        for (int kc = 0; kc < 2; kc++){
            unsigned bf[2][4];
            #pragma unroll
            for (int ng = 0; ng < 2; ng++){
                const int off = (warpN + ng*16 + lr + (grp>>1)*8)*GS2 + kc*16 + (grp&1)*8;
                ldsm4(bf[ng], SBf + off);
            }
            #pragma unroll
            for (int mt = 0; mt < 4; mt++){
                const int off = (warpM + mt*16 + lr + (grp&1)*8)*GS2 + kc*16 + (grp>>1)*8;
                unsigned af[4];
                ldsm4(af, SAf + off);
                #pragma unroll
                for (int ng = 0; ng < 2; ng++)
                    #pragma unroll
                    for (int hf = 0; hf < 2; hf++){
                        const int nt = ng*2 + hf;
                        mma16h(acc[mt][nt], af, bf[ng][2*hf], bf[ng][2*hf+1]);
                    }
            }
        }
        __syncthreads();
    }

    const float inv1024 = 1.f/1024.f;
    #pragma unroll
    for (int mt = 0; mt < 4; mt++){
        const int row = m0 + warpM + mt*16 + g;
        #pragma unroll
        for (int nt = 0; nt < 4; nt++){
            const int col = n0 + warpN + nt*8 + 2*t4;
            const float bv0 = ga.bias[col], bv1 = ga.bias[col+1];
            float a0 = acc[mt][nt][0]*inv1024 + bv0, a1 = acc[mt][nt][1]*inv1024 + bv1;
            float a2 = acc[mt][nt][2]*inv1024 + bv0, a3 = acc[mt][nt][3]*inv1024 + bv1;
            if (OMODE == 1){
                a0 *= ga.scale; a1 *= ga.scale; a2 *= ga.scale; a3 *= ga.scale;
                *(unsigned*)(ga.Cf + (size_t)row    *N + col) = pack2h(a0, a1);
                *(unsigned*)(ga.Cf + (size_t)(row+8)*N + col) = pack2h(a2, a3);
            } else {
                *(float2*)(ga.C + (size_t)row    *N + col) = make_float2(a0, a1);
                *(float2*)(ga.C + (size_t)(row+8)*N + col) = make_float2(a2, a3);
            }
        }
    }
}

__global__ __launch_bounds__(256, 2) void gemm1h_qkv(
    GemmArgs a0, GemmArgs a1, GemmArgs a2, int M, int N, int K)
{
    const GemmArgs& ga = (blockIdx.z == 0) ? a0 : (blockIdx.z == 1) ? a1 : a2;
    gemm1h_body<1>(ga, M, N, K);
}
__global__ __launch_bounds__(256, 2) void gemm1h_out(
    GemmArgs ga, int M, int N, int K)
{
    gemm1h_body<0>(ga, M, N, K);
}

// ---------------------------------------------------------------------------
// FP16 flash attention (single-term). Block = 128 q-rows of one (b,h);
// 8 warps x 16 rows; 64 keys/iter; cp.async 2-stage K/V pipeline; P in regs.
// Q pre-scaled by 1/sqrt(dk). Output: single fp16 plane.
// ---------------------------------------------------------------------------
#define AS   72                 // fp16 elems per smem row (144B)
#define ATE  (64*AS)            // one K or V plane (4608)
#define ASTG (2*ATE)            // stage: K|V (9216)

__global__ __launch_bounds__(256, 2) void attn_mma(
    const __half* __restrict__ Qf_g, const __half* __restrict__ Kf_g,
    const __half* __restrict__ Vf_g, __half* __restrict__ Of_g)
{
    extern __shared__ __half sh[];
    const int tid  = threadIdx.x;
    const int warp = tid >> 5, lane = tid & 31;
    const int g = lane >> 2, t4 = lane & 3;
    const int lr = lane & 7, grp = lane >> 3;
    const int qb = (int)gridDim.x - 1 - (int)blockIdx.x;   // long blocks first
    const int h = blockIdx.y, b = blockIdx.z;
    const int w16 = warp * 16;
    const int qrow0 = qb * 128;
    const size_t hoff = (size_t)h * DKH;

    // ---- Q tile (128 rows) -> transient smem, then fragments ----
    #pragma unroll
    for (int j = 0; j < 4; j++){
        const int cc = j*256 + tid;            // 1024 chunks
        const int r = cc >> 3, col = (cc & 7) * 8;
        cp16(sh + r*AS + col,
             Qf_g + (size_t)(b*SEQ + qrow0 + r)*DM + hoff + col);
    }
    cpcommit(); cpwait<0>();
    __syncthreads();

    unsigned qf[4][4];
    #pragma unroll
    for (int kc = 0; kc < 4; kc++){
        const int off = (w16 + lr + (grp&1)*8)*AS + kc*16 + (grp>>1)*8;
        ldsm4(qf[kc], sh + off);
    }
    __syncthreads();   // all warps done with Q smem before K/V overwrite

    auto issue = [&](int kt){
        const int st = (kt & 1) * ASTG;
        #pragma unroll
        for (int pl = 0; pl < 2; pl++){
            const __half* base = pl ? Vf_g : Kf_g;
            #pragma unroll
            for (int j = 0; j < 2; j++){
                const int cc = j*256 + tid;    // 512 chunks per plane
                const int r = cc >> 3, col = (cc & 7) * 8;
                cp16(sh + st + pl*ATE + r*AS + col,
                     base + (size_t)(b*SEQ + kt*64 + r)*DM + hoff + col);
            }
        }
        cpcommit();
    };

    float o[8][4];
    #pragma unroll
    for (int nn=0;nn<8;nn++)
        #pragma unroll
        for (int c=0;c<4;c++) o[nn][c] = 0.f;
    float mrow0 = -1e30f, mrow1 = -1e30f, lrow0 = 0.f, lrow1 = 0.f;

    const int nkt = 2*qb + 2;   // key tiles of 64 covering [0, qrow0+128)
    issue(0);
    for (int kt = 0; kt < nkt; kt++){
        if (kt + 1 < nkt){ issue(kt+1); cpwait<1>(); } else cpwait<0>();
        __syncthreads();

        const __half* Ks = sh + (kt & 1) * ASTG;
        const __half* Vs = Ks + ATE;

        // ---- S = Q K^T ----
        float s[8][4];
        #pragma unroll
        for (int nn=0;nn<8;nn++)
            #pragma unroll
            for (int c=0;c<4;c++) s[nn][c] = 0.f;

        #pragma unroll
        for (int kc = 0; kc < 4; kc++){
            #pragma unroll
            for (int ng = 0; ng < 4; ng++){
                unsigned k4[4];
                const int off = (ng*16 + lr + (grp>>1)*8)*AS + kc*16 + (grp&1)*8;
                ldsm4(k4, Ks + off);
                mma16h(s[ng*2  ], qf[kc], k4[0], k4[1]);
                mma16h(s[ng*2+1], qf[kc], k4[2], k4[3]);
            }
        }

        // ---- causal mask (only tiles crossing this warp's diagonal) ----
        if (kt*64 + 63 > qrow0 + w16){
            const int r0 = qrow0 + w16 + g;
            #pragma unroll
            for (int nn = 0; nn < 8; nn++){
                const int col = kt*64 + nn*8 + 2*t4;
                if (col     > r0    ) s[nn][0] = -1e30f;
                if (col + 1 > r0    ) s[nn][1] = -1e30f;
                if (col     > r0 + 8) s[nn][2] = -1e30f;
                if (col + 1 > r0 + 8) s[nn][3] = -1e30f;
            }
        }

        // ---- online softmax ----
        float mx0 = -1e30f, mx1 = -1e30f;
        #pragma unroll
        for (int nn = 0; nn < 8; nn++){
            mx0 = fmaxf(mx0, fmaxf(s[nn][0], s[nn][1]));
            mx1 = fmaxf(mx1, fmaxf(s[nn][2], s[nn][3]));
        }
        mx0 = fmaxf(mx0, __shfl_xor_sync(0xffffffffu, mx0, 1));
        mx0 = fmaxf(mx0, __shfl_xor_sync(0xffffffffu, mx0, 2));
        mx1 = fmaxf(mx1, __shfl_xor_sync(0xffffffffu, mx1, 1));
        mx1 = fmaxf(mx1, __shfl_xor_sync(0xffffffffu, mx1, 2));

        const float mn0 = fmaxf(mrow0, mx0), mn1 = fmaxf(mrow1, mx1);
        const float cr0 = __expf(mrow0 - mn0), cr1 = __expf(mrow1 - mn1);
        lrow0 *= cr0; lrow1 *= cr1;
        #pragma unroll
        for (int nn = 0; nn < 8; nn++){
            o[nn][0] *= cr0; o[nn][1] *= cr0;
            o[nn][2] *= cr1; o[nn][3] *= cr1;
        }
        mrow0 = mn0; mrow1 = mn1;

        #pragma unroll
        for (int nn = 0; nn < 8; nn++){
            const float p0 = __expf(s[nn][0] - mn0);
            const float p1 = __expf(s[nn][1] - mn0);
            const float p2 = __expf(s[nn][2] - mn1);
            const float p3 = __expf(s[nn][3] - mn1);
            lrow0 += p0 + p1;
            lrow1 += p2 + p3;
            s[nn][0] = p0; s[nn][1] = p1; s[nn][2] = p2; s[nn][3] = p3;
        }

        // ---- O += P V (P fp16 in regs, V via ldmatrix.trans) ----
        #pragma unroll
        for (int kc = 0; kc < 4; kc++){
            const float* sA = s[2*kc];
            const float* sB = s[2*kc+1];
            unsigned p4[4];
            p4[0] = pack2h(sA[0], sA[1]);
            p4[1] = pack2h(sA[2], sA[3]);
            p4[2] = pack2h(sB[0], sB[1]);
            p4[3] = pack2h(sB[2], sB[3]);
            #pragma unroll
            for (int dt = 0; dt < 4; dt++){
                unsigned v4[4];
                const int off = (kc*16 + lr + (grp&1)*8)*AS + dt*16 + (grp>>1)*8;
                ldsm4t(v4, Vs + off);
                mma16h(o[dt*2  ], p4, v4[0], v4[1]);
                mma16h(o[dt*2+1], p4, v4[2], v4[3]);
            }
        }
        __syncthreads();   // all warps done reading this stage
    }

    // ---- final normalize + fp16 store ----
    lrow0 += __shfl_xor_sync(0xffffffffu, lrow0, 1);
    lrow0 += __shfl_xor_sync(0xffffffffu, lrow0, 2);
    lrow1 += __shfl_xor_sync(0xffffffffu, lrow1, 1);
    lrow1 += __shfl_xor_sync(0xffffffffu, lrow1, 2);
    const float inv0 = 1.f / lrow0, inv1 = 1.f / lrow1;

    const int rowg = b*SEQ + qrow0 + w16 + g;
    const size_t base0 = (size_t)rowg    *DM + hoff;
    const size_t base1 = (size_t)(rowg+8)*DM + hoff;
    #pragma unroll
    for (int nn = 0; nn < 8; nn++){
        const int col = nn*8 + 2*t4;
        *(unsigned*)(Of_g + base0 + col) = pack2h(o[nn][0]*inv0, o[nn][1]*inv0);
        *(unsigned*)(Of_g + base1 + col) = pack2h(o[nn][2]*inv1, o[nn][3]*inv1);
    }
}

// ---------------------------------------------------------------------------
extern "C" void kernel_launch(void* const* d_in, const int* in_sizes, int n_in,
                              void* d_out, int out_size)
{
    const float* q   = (const float*)d_in[0];
    const float* k   = (const float*)d_in[1];
    const float* v   = (const float*)d_in[2];
    // d_in[3]: causal mask (tril) — computed analytically in-kernel.
    const float* w_q = (const float*)d_in[4];
    const float* b_q = (const float*)d_in[5];
    const float* w_k = (const float*)d_in[6];
    const float* b_k = (const float*)d_in[7];
    const float* w_v = (const float*)d_in[8];
    const float* b_v = (const float*)d_in[9];
    const float* w_o = (const float*)d_in[10];
    const float* b_o = (const float*)d_in[11];
    float* out = (float*)d_out;

    __half *xq,*xk,*xv, *wq,*wk,*wv,*wo, *Qf,*Kf,*Vf,*Of;
    cudaGetSymbolAddress((void**)&xq, g_xq); cudaGetSymbolAddress((void**)&xk, g_xk);
    cudaGetSymbolAddress((void**)&xv, g_xv);
    cudaGetSymbolAddress((void**)&wq, g_wq); cudaGetSymbolAddress((void**)&wk, g_wk);
    cudaGetSymbolAddress((void**)&wv, g_wv); cudaGetSymbolAddress((void**)&wo, g_wo);
    cudaGetSymbolAddress((void**)&Qf, g_Qf); cudaGetSymbolAddress((void**)&Kf, g_Kf);
    cudaGetSymbolAddress((void**)&Vf, g_Vf); cudaGetSymbolAddress((void**)&Of, g_Of);

    const int gemm_smem = 2 * GSTG * (int)sizeof(__half);   // 40960
    const int attn_smem = 2 * ASTG * (int)sizeof(__half);   // 36864
    cudaFuncSetAttribute(gemm1h_qkv, cudaFuncAttributeMaxDynamicSharedMemorySize, gemm_smem);
    cudaFuncSetAttribute(gemm1h_out, cudaFuncAttributeMaxDynamicSharedMemorySize, gemm_smem);
    cudaFuncSetAttribute(attn_mma,   cudaFuncAttributeMaxDynamicSharedMemorySize, attn_smem);

    // ---- converts ----
    const int n4i = NELEM / 4, n4w = WELEM / 4;
    dim3 cgrid(n4i / (256*4), 1, 3);
    conv_in<<<cgrid, 256>>>((const float4*)q, (const float4*)k, (const float4*)v,
                            (uint2*)xq, (uint2*)xk, (uint2*)xv, n4i);
    dim3 wgrid(n4w / (256*4), 1, 4);
    conv_w<<<wgrid, 256>>>((const float4*)w_q, (const float4*)w_k,
                           (const float4*)w_v, (const float4*)w_o,
                           (uint2*)wq, (uint2*)wk, (uint2*)wv, (uint2*)wo, n4w);

    // ---- fused QKV projections (fp16 outputs; Q pre-scaled by 1/8) ----
    GemmArgs gq = {xq, wq, b_q, nullptr, Qf, 0.125f};
    GemmArgs gk = {xk, wk, b_k, nullptr, Kf, 1.0f};
    GemmArgs gv = {xv, wv, b_v, nullptr, Vf, 1.0f};
    dim3 ggrid(DM / 128, MROWS / 128, 3);   // (8, 64, 3)
    gemm1h_qkv<<<ggrid, 256, gemm_smem>>>(gq, gk, gv, MROWS, DM, DM);

    dim3 agrid(SEQ / 128, NH, BATCH);       // (16, 16, 4)
    attn_mma<<<agrid, 256, attn_smem>>>(Qf, Kf, Vf, Of);

    GemmArgs go = {Of, wo, b_o, out, nullptr, 1.0f};
    dim3 ogrid(DM / 128, MROWS / 128, 1);
    gemm1h_out<<<ogrid, 256, gemm_smem>>>(go, MROWS, DM, DM);
}